// round 4
// baseline (speedup 1.0000x reference)
#include <cuda_runtime.h>
#include <math.h>
#include <stdint.h>

// ---------------------------------------------------------------------------
// FeatureMixer: B=4,Q=900,H=4,P=32,C=64, FEATS=QUERY=256, E=2, EP=64, D1=64
//   params = qf @ W_gen + b_gen           (3600 x 24576, K=256)   tf32 mma
//   per (row,h): channel mix + gelu + LN2d, spatial mix + gelu + LN2d (fused)
//   out    = mid @ W_out + b_out, LN(256) (3600 x 256, K=16384)   tf32 mma, split-K
// ---------------------------------------------------------------------------

#define DEV __device__ __forceinline__

constexpr int MROWS = 3600;      // B*Q
constexpr int N1    = 24576;     // TOTAL params per query
constexpr int K1    = 256;       // query dim
constexpr int NMID  = 16384;     // H*EP*D1
constexpr int NOUT  = 256;
constexpr int SPLITK = 8;        // GEMM3 split-K

// scratch (static device allocations are allowed)
__device__ float g_params[(size_t)MROWS * N1];                  // 354 MB
__device__ float g_mid[(size_t)MROWS * NMID];                   // 236 MB
__device__ float g_part[(size_t)SPLITK * MROWS * NOUT];         // 29.5 MB

DEV uint32_t f2tf(float f) {
    uint32_t u;
    asm("cvt.rna.tf32.f32 %0, %1;" : "=r"(u) : "f"(f));
    return u;
}

DEV void mma8(float* c, const uint32_t* a, const uint32_t* b) {
    asm volatile(
        "mma.sync.aligned.m16n8k8.row.col.f32.tf32.tf32.f32 "
        "{%0,%1,%2,%3}, {%4,%5,%6,%7}, {%8,%9}, {%0,%1,%2,%3};\n"
        : "+f"(c[0]), "+f"(c[1]), "+f"(c[2]), "+f"(c[3])
        : "r"(a[0]), "r"(a[1]), "r"(a[2]), "r"(a[3]), "r"(b[0]), "r"(b[1]));
}

DEV float gelu_exact(float x) {
    return 0.5f * x * (1.0f + erff(x * 0.70710678118654752f));
}

// block-wide sum + sumsq over 256 threads (8 warps)
DEV void block_reduce2(float& s, float& ss, float* red, int tid) {
#pragma unroll
    for (int o = 16; o > 0; o >>= 1) {
        s  += __shfl_xor_sync(0xffffffffu, s, o);
        ss += __shfl_xor_sync(0xffffffffu, ss, o);
    }
    if ((tid & 31) == 0) { red[tid >> 5] = s; red[8 + (tid >> 5)] = ss; }
    __syncthreads();
    s = 0.f; ss = 0.f;
#pragma unroll
    for (int i = 0; i < 8; ++i) { s += red[i]; ss += red[8 + i]; }
}

// ---------------------------------------------------------------------------
// GEMM1: g_params = qf(3600x256) @ W_gen(256x24576) + b_gen
// CTA tile 128x128, BK=32, 8 warps (2x4), warp tile 64x32, tf32 m16n8k8
// ---------------------------------------------------------------------------
__global__ void __launch_bounds__(256, 1)
gemm1_kernel(const float* __restrict__ A, const float* __restrict__ B,
             const float* __restrict__ bias) {
    __shared__ uint32_t As[128 * 36];   // pad 36 -> conflict-free frag loads
    __shared__ uint32_t Bs[32 * 132];   // pad 132

    const int tid  = threadIdx.x;
    const int lane = tid & 31, warp = tid >> 5;
    const int g = lane >> 2, tg = lane & 3;
    const int wr = warp >> 2, wc = warp & 3;          // 2 x 4 warp grid
    const int mBase = blockIdx.y * 128, nBase = blockIdx.x * 128;

    float acc[4][4][4];
#pragma unroll
    for (int i = 0; i < 4; ++i)
#pragma unroll
        for (int j = 0; j < 4; ++j)
#pragma unroll
            for (int k = 0; k < 4; ++k) acc[i][j][k] = 0.f;

    const int arr = tid >> 3;           // 0..31  (A tile row group)
    const int ac_ = (tid & 7) * 4;      // A tile col (float4)
    const int brr = tid >> 5;           // 0..7
    const int bcc = (tid & 31) * 4;     // B tile col (float4)

    for (int kt = 0; kt < K1 / 32; ++kt) {
        const int k0 = kt * 32;
        float4 av[4], bv[4];
#pragma unroll
        for (int i = 0; i < 4; ++i) {
            int r = arr + i * 32, gr = mBase + r;
            av[i] = (gr < MROWS) ? *(const float4*)(A + (size_t)gr * K1 + k0 + ac_)
                                 : make_float4(0.f, 0.f, 0.f, 0.f);
        }
#pragma unroll
        for (int i = 0; i < 4; ++i) {
            int r = brr + i * 8;
            bv[i] = *(const float4*)(B + (size_t)(k0 + r) * N1 + nBase + bcc);
        }
        __syncthreads();
#pragma unroll
        for (int i = 0; i < 4; ++i) {
            int r = arr + i * 32;
            As[r * 36 + ac_ + 0] = f2tf(av[i].x);
            As[r * 36 + ac_ + 1] = f2tf(av[i].y);
            As[r * 36 + ac_ + 2] = f2tf(av[i].z);
            As[r * 36 + ac_ + 3] = f2tf(av[i].w);
        }
#pragma unroll
        for (int i = 0; i < 4; ++i) {
            int r = brr + i * 8;
            Bs[r * 132 + bcc + 0] = f2tf(bv[i].x);
            Bs[r * 132 + bcc + 1] = f2tf(bv[i].y);
            Bs[r * 132 + bcc + 2] = f2tf(bv[i].z);
            Bs[r * 132 + bcc + 3] = f2tf(bv[i].w);
        }
        __syncthreads();

#pragma unroll
        for (int kk = 0; kk < 32; kk += 8) {
            uint32_t af[4][4], bf[4][2];
#pragma unroll
            for (int mi = 0; mi < 4; ++mi) {
                int row = wr * 64 + mi * 16 + g;
                af[mi][0] = As[row * 36 + kk + tg];
                af[mi][1] = As[(row + 8) * 36 + kk + tg];
                af[mi][2] = As[row * 36 + kk + tg + 4];
                af[mi][3] = As[(row + 8) * 36 + kk + tg + 4];
            }
#pragma unroll
            for (int ni = 0; ni < 4; ++ni) {
                int col = wc * 32 + ni * 8 + g;
                bf[ni][0] = Bs[(kk + tg) * 132 + col];
                bf[ni][1] = Bs[(kk + tg + 4) * 132 + col];
            }
#pragma unroll
            for (int mi = 0; mi < 4; ++mi)
#pragma unroll
                for (int ni = 0; ni < 4; ++ni) mma8(acc[mi][ni], af[mi], bf[ni]);
        }
    }

#pragma unroll
    for (int mi = 0; mi < 4; ++mi) {
        int r0 = mBase + wr * 64 + mi * 16 + g;
#pragma unroll
        for (int ni = 0; ni < 4; ++ni) {
            int c0 = nBase + wc * 32 + ni * 8 + tg * 2;
            float b0 = bias[c0], b1 = bias[c0 + 1];
            if (r0 < MROWS) {
                g_params[(size_t)r0 * N1 + c0]     = acc[mi][ni][0] + b0;
                g_params[(size_t)r0 * N1 + c0 + 1] = acc[mi][ni][1] + b1;
            }
            if (r0 + 8 < MROWS) {
                g_params[(size_t)(r0 + 8) * N1 + c0]     = acc[mi][ni][2] + b0;
                g_params[(size_t)(r0 + 8) * N1 + c0 + 1] = acc[mi][ni][3] + b1;
            }
        }
    }
}

// ---------------------------------------------------------------------------
// Mid kernel: one CTA per (b,q) row. For each head:
//   out1 = sampled(32x64) @ p1(64x64); gelu; LN over 2048
//   out2 = p2(64x32) @ out1(32x64);    gelu; LN over 4096 -> g_mid
// ---------------------------------------------------------------------------
__global__ void __launch_bounds__(256, 1)
mid_kernel(const float* __restrict__ sampled) {
    __shared__ __align__(16) float sA[4096];  // p1 (c-major 64x64)
    __shared__ __align__(16) float sB[2048];  // sampled, then p2
    __shared__ __align__(16) float sC[2048];  // out1 (normalized)
    __shared__ float red[16];

    const int row = blockIdx.x, t = threadIdx.x;
    const float* prow = g_params + (size_t)row * N1;
    const float* srow = sampled + (size_t)row * 8192;
    float* mrow = g_mid + (size_t)row * NMID;

    const int dg = t & 15;   // d group: d = dg*4..dg*4+3
    const int pg = t >> 4;   // 0..15

    for (int h = 0; h < 4; ++h) {
        for (int i = t; i < 1024; i += 256)
            ((float4*)sA)[i] = ((const float4*)(prow + h * 4096))[i];
        for (int i = t; i < 512; i += 256)
            ((float4*)sB)[i] = ((const float4*)(srow + h * 2048))[i];
        __syncthreads();

        // ---- channel mix: thread computes 2 p rows x 4 d cols ----
        const int p0 = pg * 2, p1 = pg * 2 + 1;
        float a0[4] = {0.f, 0.f, 0.f, 0.f}, a1[4] = {0.f, 0.f, 0.f, 0.f};
#pragma unroll 8
        for (int c = 0; c < 64; ++c) {
            float b0 = sB[p0 * 64 + c], b1 = sB[p1 * 64 + c];
            float4 a = *(const float4*)(sA + c * 64 + dg * 4);
            a0[0] += b0 * a.x; a0[1] += b0 * a.y; a0[2] += b0 * a.z; a0[3] += b0 * a.w;
            a1[0] += b1 * a.x; a1[1] += b1 * a.y; a1[2] += b1 * a.z; a1[3] += b1 * a.w;
        }
        float s = 0.f, ss = 0.f;
#pragma unroll
        for (int j = 0; j < 4; ++j) {
            a0[j] = gelu_exact(a0[j]); a1[j] = gelu_exact(a1[j]);
            s += a0[j] + a1[j]; ss += a0[j] * a0[j] + a1[j] * a1[j];
        }
        block_reduce2(s, ss, red, t);
        float mean = s * (1.f / 2048.f);
        float inv  = rsqrtf(ss * (1.f / 2048.f) - mean * mean + 1e-5f);
        {
            float4 w0 = make_float4((a0[0] - mean) * inv, (a0[1] - mean) * inv,
                                    (a0[2] - mean) * inv, (a0[3] - mean) * inv);
            float4 w1 = make_float4((a1[0] - mean) * inv, (a1[1] - mean) * inv,
                                    (a1[2] - mean) * inv, (a1[3] - mean) * inv);
            *(float4*)(sC + p0 * 64 + dg * 4) = w0;
            *(float4*)(sC + p1 * 64 + dg * 4) = w1;
        }
        // p2 into sB (all sB reads completed before block_reduce2's barrier)
        for (int i = t; i < 512; i += 256)
            ((float4*)sB)[i] = ((const float4*)(prow + 16384 + h * 2048))[i];
        __syncthreads();

        // ---- spatial mix: thread computes 4 e rows x 4 d cols ----
        float acc2[4][4];
#pragma unroll
        for (int i = 0; i < 4; ++i)
#pragma unroll
            for (int j = 0; j < 4; ++j) acc2[i][j] = 0.f;
#pragma unroll 4
        for (int p = 0; p < 32; ++p) {
            float4 cv = *(const float4*)(sC + p * 64 + dg * 4);
#pragma unroll
            for (int i = 0; i < 4; ++i) {
                float bb = sB[(pg * 4 + i) * 32 + p];
                acc2[i][0] += bb * cv.x; acc2[i][1] += bb * cv.y;
                acc2[i][2] += bb * cv.z; acc2[i][3] += bb * cv.w;
            }
        }
        s = 0.f; ss = 0.f;
#pragma unroll
        for (int i = 0; i < 4; ++i)
#pragma unroll
            for (int j = 0; j < 4; ++j) {
                acc2[i][j] = gelu_exact(acc2[i][j]);
                s += acc2[i][j]; ss += acc2[i][j] * acc2[i][j];
            }
        block_reduce2(s, ss, red, t);
        mean = s * (1.f / 4096.f);
        inv  = rsqrtf(ss * (1.f / 4096.f) - mean * mean + 1e-5f);
#pragma unroll
        for (int i = 0; i < 4; ++i) {
            float4 w = make_float4((acc2[i][0] - mean) * inv, (acc2[i][1] - mean) * inv,
                                   (acc2[i][2] - mean) * inv, (acc2[i][3] - mean) * inv);
            *(float4*)(mrow + h * 4096 + (pg * 4 + i) * 64 + dg * 4) = w;
        }
        __syncthreads();
    }
}

// ---------------------------------------------------------------------------
// GEMM3: g_part[s] = g_mid(3600x16384) @ W_out(16384x256), split-K over z
// CTA tile 128x64, BK=32, 8 warps (4x2), warp tile 32x32
// ---------------------------------------------------------------------------
__global__ void __launch_bounds__(256, 1)
gemm3_kernel(const float* __restrict__ B) {
    __shared__ uint32_t As[128 * 36];
    __shared__ uint32_t Bs[32 * 68];

    const int tid  = threadIdx.x;
    const int lane = tid & 31, warp = tid >> 5;
    const int g = lane >> 2, tg = lane & 3;
    const int wr = warp >> 1, wc = warp & 1;          // 4 x 2 warp grid
    const int mBase = blockIdx.y * 128, nBase = blockIdx.x * 64;
    const int kOff  = blockIdx.z * (NMID / SPLITK);   // 2048

    float acc[2][4][4];
#pragma unroll
    for (int i = 0; i < 2; ++i)
#pragma unroll
        for (int j = 0; j < 4; ++j)
#pragma unroll
            for (int k = 0; k < 4; ++k) acc[i][j][k] = 0.f;

    const int arr = tid >> 3;        // 0..31
    const int ac_ = (tid & 7) * 4;
    const int brr = tid >> 4;        // 0..15
    const int bcc = (tid & 15) * 4;

    for (int kt = 0; kt < (NMID / SPLITK) / 32; ++kt) {  // 64 iters
        const int k0 = kOff + kt * 32;
        float4 av[4], bv[2];
#pragma unroll
        for (int i = 0; i < 4; ++i) {
            int r = arr + i * 32, gr = mBase + r;
            av[i] = (gr < MROWS) ? *(const float4*)(g_mid + (size_t)gr * NMID + k0 + ac_)
                                 : make_float4(0.f, 0.f, 0.f, 0.f);
        }
#pragma unroll
        for (int i = 0; i < 2; ++i) {
            int r = brr + i * 16;
            bv[i] = *(const float4*)(B + (size_t)(k0 + r) * NOUT + nBase + bcc);
        }
        __syncthreads();
#pragma unroll
        for (int i = 0; i < 4; ++i) {
            int r = arr + i * 32;
            As[r * 36 + ac_ + 0] = f2tf(av[i].x);
            As[r * 36 + ac_ + 1] = f2tf(av[i].y);
            As[r * 36 + ac_ + 2] = f2tf(av[i].z);
            As[r * 36 + ac_ + 3] = f2tf(av[i].w);
        }
#pragma unroll
        for (int i = 0; i < 2; ++i) {
            int r = brr + i * 16;
            Bs[r * 68 + bcc + 0] = f2tf(bv[i].x);
            Bs[r * 68 + bcc + 1] = f2tf(bv[i].y);
            Bs[r * 68 + bcc + 2] = f2tf(bv[i].z);
            Bs[r * 68 + bcc + 3] = f2tf(bv[i].w);
        }
        __syncthreads();

#pragma unroll
        for (int kk = 0; kk < 32; kk += 8) {
            uint32_t af[2][4], bf[4][2];
#pragma unroll
            for (int mi = 0; mi < 2; ++mi) {
                int rrow = wr * 32 + mi * 16 + g;
                af[mi][0] = As[rrow * 36 + kk + tg];
                af[mi][1] = As[(rrow + 8) * 36 + kk + tg];
                af[mi][2] = As[rrow * 36 + kk + tg + 4];
                af[mi][3] = As[(rrow + 8) * 36 + kk + tg + 4];
            }
#pragma unroll
            for (int ni = 0; ni < 4; ++ni) {
                int col = wc * 32 + ni * 8 + g;
                bf[ni][0] = Bs[(kk + tg) * 68 + col];
                bf[ni][1] = Bs[(kk + tg + 4) * 68 + col];
            }
#pragma unroll
            for (int mi = 0; mi < 2; ++mi)
#pragma unroll
                for (int ni = 0; ni < 4; ++ni) mma8(acc[mi][ni], af[mi], bf[ni]);
        }
    }

    const size_t partBase = (size_t)blockIdx.z * MROWS * NOUT;
#pragma unroll
    for (int mi = 0; mi < 2; ++mi) {
        int r0 = mBase + wr * 32 + mi * 16 + g;
#pragma unroll
        for (int ni = 0; ni < 4; ++ni) {
            int c0 = nBase + wc * 32 + ni * 8 + tg * 2;
            if (r0 < MROWS) {
                g_part[partBase + (size_t)r0 * NOUT + c0]     = acc[mi][ni][0];
                g_part[partBase + (size_t)r0 * NOUT + c0 + 1] = acc[mi][ni][1];
            }
            if (r0 + 8 < MROWS) {
                g_part[partBase + (size_t)(r0 + 8) * NOUT + c0]     = acc[mi][ni][2];
                g_part[partBase + (size_t)(r0 + 8) * NOUT + c0 + 1] = acc[mi][ni][3];
            }
        }
    }
}

// ---------------------------------------------------------------------------
// Epilogue: deterministic split-K reduce + bias + affine LayerNorm(256)
// ---------------------------------------------------------------------------
__global__ void __launch_bounds__(256, 1)
out_ln_kernel(const float* __restrict__ b_out, const float* __restrict__ ln_w,
              const float* __restrict__ ln_b, float* __restrict__ out) {
    __shared__ float red[16];
    const int row = blockIdx.x, t = threadIdx.x;
    float v = b_out[t];
#pragma unroll
    for (int sp = 0; sp < SPLITK; ++sp)
        v += g_part[(size_t)sp * MROWS * NOUT + (size_t)row * NOUT + t];
    float s = v, ss = v * v;
    block_reduce2(s, ss, red, t);
    float mean = s * (1.f / 256.f);
    float inv  = rsqrtf(ss * (1.f / 256.f) - mean * mean + 1e-5f);
    out[(size_t)row * NOUT + t] = (v - mean) * inv * ln_w[t] + ln_b[t];
}

// ---------------------------------------------------------------------------
extern "C" void kernel_launch(void* const* d_in, const int* in_sizes, int n_in,
                              void* d_out, int out_size) {
    (void)in_sizes; (void)n_in; (void)out_size;
    const float* qf      = (const float*)d_in[0];
    const float* sampled = (const float*)d_in[1];
    const float* W_gen   = (const float*)d_in[2];
    const float* b_gen   = (const float*)d_in[3];
    const float* W_out   = (const float*)d_in[4];
    const float* b_out   = (const float*)d_in[5];
    const float* ln_w    = (const float*)d_in[6];
    const float* ln_b    = (const float*)d_in[7];

    gemm1_kernel<<<dim3(N1 / 128, (MROWS + 127) / 128), 256>>>(qf, W_gen, b_gen);
    mid_kernel<<<MROWS, 256>>>(sampled);
    gemm3_kernel<<<dim3(NOUT / 64, (MROWS + 127) / 128, SPLITK), 256>>>(W_out);
    out_ln_kernel<<<MROWS, 256>>>(b_out, ln_w, ln_b, (float*)d_out);
}

// round 5
// speedup vs baseline: 1.1293x; 1.1293x over previous
#include <cuda_runtime.h>
#include <math.h>
#include <stdint.h>

// ---------------------------------------------------------------------------
// FeatureMixer: B=4,Q=900,H=4,P=32,C=64, FEATS=QUERY=256, E=2, EP=64, D1=64
//   params = qf @ W_gen + b_gen           (3600 x 24576, K=256)   tf32 mma
//   per (row,h): channel mix + gelu + LN2d, spatial mix + gelu + LN2d
//                (fused, 3xTF32 tensor-core mma)
//   out    = mid @ W_out + b_out, LN(256) (3600 x 256, K=16384)   tf32 mma, split-K
// ---------------------------------------------------------------------------

#define DEV __device__ __forceinline__

constexpr int MROWS = 3600;      // B*Q
constexpr int N1    = 24576;     // TOTAL params per query
constexpr int K1    = 256;       // query dim
constexpr int NMID  = 16384;     // H*EP*D1
constexpr int NOUT  = 256;
constexpr int SPLITK = 8;        // GEMM3 split-K

__device__ float g_params[(size_t)MROWS * N1];
__device__ float g_mid[(size_t)MROWS * NMID];
__device__ float g_part[(size_t)SPLITK * MROWS * NOUT];

DEV uint32_t f2tf(float f) {
    uint32_t u;
    asm("cvt.rna.tf32.f32 %0, %1;" : "=r"(u) : "f"(f));
    return u;
}

// hi/lo split for 3xTF32 (fp32-accurate tensor GEMM)
DEV void split2(float x, uint32_t& hi, uint32_t& lo) {
    uint32_t h = f2tf(x);
    hi = h;
    lo = f2tf(x - __uint_as_float(h));
}

DEV void mma8(float* c, const uint32_t* a, const uint32_t* b) {
    asm volatile(
        "mma.sync.aligned.m16n8k8.row.col.f32.tf32.tf32.f32 "
        "{%0,%1,%2,%3}, {%4,%5,%6,%7}, {%8,%9}, {%0,%1,%2,%3};\n"
        : "+f"(c[0]), "+f"(c[1]), "+f"(c[2]), "+f"(c[3])
        : "r"(a[0]), "r"(a[1]), "r"(a[2]), "r"(a[3]), "r"(b[0]), "r"(b[1]));
}

DEV float gelu_exact(float x) {
    return 0.5f * x * (1.0f + erff(x * 0.70710678118654752f));
}

// block-wide sum + sumsq over 256 threads (8 warps)
DEV void block_reduce2(float& s, float& ss, float* red, int tid) {
#pragma unroll
    for (int o = 16; o > 0; o >>= 1) {
        s  += __shfl_xor_sync(0xffffffffu, s, o);
        ss += __shfl_xor_sync(0xffffffffu, ss, o);
    }
    if ((tid & 31) == 0) { red[tid >> 5] = s; red[8 + (tid >> 5)] = ss; }
    __syncthreads();
    s = 0.f; ss = 0.f;
#pragma unroll
    for (int i = 0; i < 8; ++i) { s += red[i]; ss += red[8 + i]; }
}

// ---------------------------------------------------------------------------
// GEMM1: g_params = qf(3600x256) @ W_gen(256x24576) + b_gen
// CTA tile 128x128, BK=32, 8 warps (2x4), warp tile 64x32, tf32 m16n8k8
// Register-prefetched: next tile's LDGs issue before the mma loop.
// ---------------------------------------------------------------------------
__global__ void __launch_bounds__(256, 1)
gemm1_kernel(const float* __restrict__ A, const float* __restrict__ B,
             const float* __restrict__ bias) {
    __shared__ uint32_t As[128 * 36];
    __shared__ uint32_t Bs[32 * 132];

    const int tid  = threadIdx.x;
    const int lane = tid & 31, warp = tid >> 5;
    const int g = lane >> 2, tg = lane & 3;
    const int wr = warp >> 2, wc = warp & 3;          // 2 x 4 warp grid
    const int mBase = blockIdx.y * 128, nBase = blockIdx.x * 128;

    float acc[4][4][4];
#pragma unroll
    for (int i = 0; i < 4; ++i)
#pragma unroll
        for (int j = 0; j < 4; ++j)
#pragma unroll
            for (int k = 0; k < 4; ++k) acc[i][j][k] = 0.f;

    const int arr = tid >> 3;           // 0..31
    const int ac_ = (tid & 7) * 4;
    const int brr = tid >> 5;           // 0..7
    const int bcc = (tid & 31) * 4;

    const int NT = K1 / 32;             // 8
    float4 av[4], bv[4];
#pragma unroll
    for (int i = 0; i < 4; ++i) {
        int r = arr + i * 32, gr = mBase + r;
        av[i] = (gr < MROWS) ? *(const float4*)(A + (size_t)gr * K1 + ac_)
                             : make_float4(0.f, 0.f, 0.f, 0.f);
    }
#pragma unroll
    for (int i = 0; i < 4; ++i) {
        int r = brr + i * 8;
        bv[i] = *(const float4*)(B + (size_t)r * N1 + nBase + bcc);
    }

    for (int kt = 0; kt < NT; ++kt) {
        __syncthreads();
#pragma unroll
        for (int i = 0; i < 4; ++i) {
            int r = arr + i * 32;
            As[r * 36 + ac_ + 0] = f2tf(av[i].x);
            As[r * 36 + ac_ + 1] = f2tf(av[i].y);
            As[r * 36 + ac_ + 2] = f2tf(av[i].z);
            As[r * 36 + ac_ + 3] = f2tf(av[i].w);
        }
#pragma unroll
        for (int i = 0; i < 4; ++i) {
            int r = brr + i * 8;
            Bs[r * 132 + bcc + 0] = f2tf(bv[i].x);
            Bs[r * 132 + bcc + 1] = f2tf(bv[i].y);
            Bs[r * 132 + bcc + 2] = f2tf(bv[i].z);
            Bs[r * 132 + bcc + 3] = f2tf(bv[i].w);
        }
        __syncthreads();

        // prefetch next tile while the mma loop runs
        if (kt + 1 < NT) {
            const int k0n = (kt + 1) * 32;
#pragma unroll
            for (int i = 0; i < 4; ++i) {
                int r = arr + i * 32, gr = mBase + r;
                av[i] = (gr < MROWS)
                            ? *(const float4*)(A + (size_t)gr * K1 + k0n + ac_)
                            : make_float4(0.f, 0.f, 0.f, 0.f);
            }
#pragma unroll
            for (int i = 0; i < 4; ++i) {
                int r = brr + i * 8;
                bv[i] = *(const float4*)(B + (size_t)(k0n + r) * N1 + nBase + bcc);
            }
        }

#pragma unroll
        for (int kk = 0; kk < 32; kk += 8) {
            uint32_t af[4][4], bf[4][2];
#pragma unroll
            for (int mi = 0; mi < 4; ++mi) {
                int row = wr * 64 + mi * 16 + g;
                af[mi][0] = As[row * 36 + kk + tg];
                af[mi][1] = As[(row + 8) * 36 + kk + tg];
                af[mi][2] = As[row * 36 + kk + tg + 4];
                af[mi][3] = As[(row + 8) * 36 + kk + tg + 4];
            }
#pragma unroll
            for (int ni = 0; ni < 4; ++ni) {
                int col = wc * 32 + ni * 8 + g;
                bf[ni][0] = Bs[(kk + tg) * 132 + col];
                bf[ni][1] = Bs[(kk + tg + 4) * 132 + col];
            }
#pragma unroll
            for (int mi = 0; mi < 4; ++mi)
#pragma unroll
                for (int ni = 0; ni < 4; ++ni) mma8(acc[mi][ni], af[mi], bf[ni]);
        }
    }

#pragma unroll
    for (int mi = 0; mi < 4; ++mi) {
        int r0 = mBase + wr * 64 + mi * 16 + g;
#pragma unroll
        for (int ni = 0; ni < 4; ++ni) {
            int c0 = nBase + wc * 32 + ni * 8 + tg * 2;
            float b0 = bias[c0], b1 = bias[c0 + 1];
            if (r0 < MROWS) {
                g_params[(size_t)r0 * N1 + c0]     = acc[mi][ni][0] + b0;
                g_params[(size_t)r0 * N1 + c0 + 1] = acc[mi][ni][1] + b1;
            }
            if (r0 + 8 < MROWS) {
                g_params[(size_t)(r0 + 8) * N1 + c0]     = acc[mi][ni][2] + b0;
                g_params[(size_t)(r0 + 8) * N1 + c0 + 1] = acc[mi][ni][3] + b1;
            }
        }
    }
}

// ---------------------------------------------------------------------------
// Mid kernel (3xTF32 tensor cores): one CTA (8 warps) per (b,q) row.
// Stage A per head: O1(32x64) = S(32x64) @ P1(64x64); gelu; LN over 2048
// Stage B per head: O2(64x64) = P2(64x32) @ O1n(32x64); gelu; LN over 4096
// Fragment operands are hi/lo split at load time (3 mmas per tile-k).
// ---------------------------------------------------------------------------
__global__ void __launch_bounds__(256, 2)
mid_kernel(const float* __restrict__ sampled) {
    __shared__ __align__(16) float sP1[64 * 72];  // P1, [c*72 + d]
    __shared__ __align__(16) float sU[64 * 40];   // S [p*72+c] then P2 [e*40+p]
    __shared__ __align__(16) float sC[32 * 72];   // normalized O1 [p*72 + d]
    __shared__ float red[16];

    const int row = blockIdx.x, t = threadIdx.x;
    const int lane = t & 31, warp = t >> 5;
    const int g = lane >> 2, tg = lane & 3;
    const float* prow = g_params + (size_t)row * N1;
    const float* srow = sampled + (size_t)row * 8192;
    float* mrow = g_mid + (size_t)row * NMID;

    const int mA = (warp & 1) * 16;        // stage A: 2x8 tile grid
    const int nA = (warp >> 1) * 16;
    const int mB = (warp >> 1) * 16;       // stage B: 4x8 tile grid
    const int nB = (warp & 1) * 32;

    for (int h = 0; h < 4; ++h) {
        __syncthreads();
        // load P1 (64x64 -> padded 72) and S (32x64 -> padded 72, in sU)
#pragma unroll
        for (int i = t; i < 1024; i += 256) {
            float4 v = ((const float4*)(prow + h * 4096))[i];
            int c = i >> 4, d = (i & 15) * 4;
            *(float4*)(sP1 + c * 72 + d) = v;
        }
#pragma unroll
        for (int i = t; i < 512; i += 256) {
            float4 v = ((const float4*)(srow + h * 2048))[i];
            int p = i >> 4, c = (i & 15) * 4;
            *(float4*)(sU + p * 72 + c) = v;
        }
        __syncthreads();

        // ---- stage A: tensor mma, M=32(p) N=64(d) K=64(c) ----
        float accA[2][4];
#pragma unroll
        for (int i = 0; i < 2; ++i)
#pragma unroll
            for (int j = 0; j < 4; ++j) accA[i][j] = 0.f;

#pragma unroll
        for (int k0 = 0; k0 < 64; k0 += 8) {
            uint32_t ahi[4], alo[4];
            split2(sU[(mA + g) * 72 + k0 + tg],     ahi[0], alo[0]);
            split2(sU[(mA + g + 8) * 72 + k0 + tg], ahi[1], alo[1]);
            split2(sU[(mA + g) * 72 + k0 + tg + 4],     ahi[2], alo[2]);
            split2(sU[(mA + g + 8) * 72 + k0 + tg + 4], ahi[3], alo[3]);
#pragma unroll
            for (int nt = 0; nt < 2; ++nt) {
                const int n0 = nA + nt * 8;
                uint32_t bhi[2], blo[2];
                split2(sP1[(k0 + tg) * 72 + n0 + g],     bhi[0], blo[0]);
                split2(sP1[(k0 + tg + 4) * 72 + n0 + g], bhi[1], blo[1]);
                mma8(accA[nt], ahi, bhi);
                mma8(accA[nt], ahi, blo);
                mma8(accA[nt], alo, bhi);
            }
        }

        float s = 0.f, ss = 0.f;
#pragma unroll
        for (int i = 0; i < 2; ++i)
#pragma unroll
            for (int j = 0; j < 4; ++j) {
                accA[i][j] = gelu_exact(accA[i][j]);
                s += accA[i][j]; ss += accA[i][j] * accA[i][j];
            }
        block_reduce2(s, ss, red, t);
        float mean = s * (1.f / 2048.f);
        float inv  = rsqrtf(ss * (1.f / 2048.f) - mean * mean + 1e-5f);
#pragma unroll
        for (int nt = 0; nt < 2; ++nt) {
            const int n0 = nA + nt * 8;
            sC[(mA + g) * 72 + n0 + 2 * tg]         = (accA[nt][0] - mean) * inv;
            sC[(mA + g) * 72 + n0 + 2 * tg + 1]     = (accA[nt][1] - mean) * inv;
            sC[(mA + g + 8) * 72 + n0 + 2 * tg]     = (accA[nt][2] - mean) * inv;
            sC[(mA + g + 8) * 72 + n0 + 2 * tg + 1] = (accA[nt][3] - mean) * inv;
        }
        // load P2 (64x32 -> padded 40) into sU (stage-A reads all done)
#pragma unroll
        for (int i = t; i < 512; i += 256) {
            float4 v = ((const float4*)(prow + 16384 + h * 2048))[i];
            int e = i >> 3, p = (i & 7) * 4;
            *(float4*)(sU + e * 40 + p) = v;
        }
        __syncthreads();

        // ---- stage B: tensor mma, M=64(e) N=64(d) K=32(p) ----
        float accB[4][4];
#pragma unroll
        for (int i = 0; i < 4; ++i)
#pragma unroll
            for (int j = 0; j < 4; ++j) accB[i][j] = 0.f;

#pragma unroll
        for (int k0 = 0; k0 < 32; k0 += 8) {
            uint32_t ahi[4], alo[4];
            split2(sU[(mB + g) * 40 + k0 + tg],     ahi[0], alo[0]);
            split2(sU[(mB + g + 8) * 40 + k0 + tg], ahi[1], alo[1]);
            split2(sU[(mB + g) * 40 + k0 + tg + 4],     ahi[2], alo[2]);
            split2(sU[(mB + g + 8) * 40 + k0 + tg + 4], ahi[3], alo[3]);
#pragma unroll
            for (int nt = 0; nt < 4; ++nt) {
                const int n0 = nB + nt * 8;
                uint32_t bhi[2], blo[2];
                split2(sC[(k0 + tg) * 72 + n0 + g],     bhi[0], blo[0]);
                split2(sC[(k0 + tg + 4) * 72 + n0 + g], bhi[1], blo[1]);
                mma8(accB[nt], ahi, bhi);
                mma8(accB[nt], ahi, blo);
                mma8(accB[nt], alo, bhi);
            }
        }

        s = 0.f; ss = 0.f;
#pragma unroll
        for (int i = 0; i < 4; ++i)
#pragma unroll
            for (int j = 0; j < 4; ++j) {
                accB[i][j] = gelu_exact(accB[i][j]);
                s += accB[i][j]; ss += accB[i][j] * accB[i][j];
            }
        block_reduce2(s, ss, red, t);
        mean = s * (1.f / 4096.f);
        inv  = rsqrtf(ss * (1.f / 4096.f) - mean * mean + 1e-5f);
        float* hrow = mrow + h * 4096;
#pragma unroll
        for (int nt = 0; nt < 4; ++nt) {
            const int n0 = nB + nt * 8;
            float2 w0 = make_float2((accB[nt][0] - mean) * inv,
                                    (accB[nt][1] - mean) * inv);
            float2 w1 = make_float2((accB[nt][2] - mean) * inv,
                                    (accB[nt][3] - mean) * inv);
            *(float2*)(hrow + (mB + g) * 64 + n0 + 2 * tg)     = w0;
            *(float2*)(hrow + (mB + g + 8) * 64 + n0 + 2 * tg) = w1;
        }
    }
}

// ---------------------------------------------------------------------------
// GEMM3: g_part[s] = g_mid(3600x16384) @ W_out(16384x256), split-K over z
// CTA tile 128x64, BK=32, 8 warps (4x2), warp tile 32x32, register-prefetched
// ---------------------------------------------------------------------------
__global__ void __launch_bounds__(256, 1)
gemm3_kernel(const float* __restrict__ B) {
    __shared__ uint32_t As[128 * 36];
    __shared__ uint32_t Bs[32 * 68];

    const int tid  = threadIdx.x;
    const int lane = tid & 31, warp = tid >> 5;
    const int g = lane >> 2, tg = lane & 3;
    const int wr = warp >> 1, wc = warp & 1;          // 4 x 2 warp grid
    const int mBase = blockIdx.y * 128, nBase = blockIdx.x * 64;
    const int kOff  = blockIdx.z * (NMID / SPLITK);   // 2048

    float acc[2][4][4];
#pragma unroll
    for (int i = 0; i < 2; ++i)
#pragma unroll
        for (int j = 0; j < 4; ++j)
#pragma unroll
            for (int k = 0; k < 4; ++k) acc[i][j][k] = 0.f;

    const int arr = tid >> 3;        // 0..31
    const int ac_ = (tid & 7) * 4;
    const int brr = tid >> 4;        // 0..15
    const int bcc = (tid & 15) * 4;

    const int NT = (NMID / SPLITK) / 32;  // 64
    float4 av[4], bv[2];
#pragma unroll
    for (int i = 0; i < 4; ++i) {
        int r = arr + i * 32, gr = mBase + r;
        av[i] = (gr < MROWS) ? *(const float4*)(g_mid + (size_t)gr * NMID + kOff + ac_)
                             : make_float4(0.f, 0.f, 0.f, 0.f);
    }
#pragma unroll
    for (int i = 0; i < 2; ++i) {
        int r = brr + i * 16;
        bv[i] = *(const float4*)(B + (size_t)(kOff + r) * NOUT + nBase + bcc);
    }

    for (int kt = 0; kt < NT; ++kt) {
        __syncthreads();
#pragma unroll
        for (int i = 0; i < 4; ++i) {
            int r = arr + i * 32;
            As[r * 36 + ac_ + 0] = f2tf(av[i].x);
            As[r * 36 + ac_ + 1] = f2tf(av[i].y);
            As[r * 36 + ac_ + 2] = f2tf(av[i].z);
            As[r * 36 + ac_ + 3] = f2tf(av[i].w);
        }
#pragma unroll
        for (int i = 0; i < 2; ++i) {
            int r = brr + i * 16;
            Bs[r * 68 + bcc + 0] = f2tf(bv[i].x);
            Bs[r * 68 + bcc + 1] = f2tf(bv[i].y);
            Bs[r * 68 + bcc + 2] = f2tf(bv[i].z);
            Bs[r * 68 + bcc + 3] = f2tf(bv[i].w);
        }
        __syncthreads();

        if (kt + 1 < NT) {
            const int k0n = kOff + (kt + 1) * 32;
#pragma unroll
            for (int i = 0; i < 4; ++i) {
                int r = arr + i * 32, gr = mBase + r;
                av[i] = (gr < MROWS)
                            ? *(const float4*)(g_mid + (size_t)gr * NMID + k0n + ac_)
                            : make_float4(0.f, 0.f, 0.f, 0.f);
            }
#pragma unroll
            for (int i = 0; i < 2; ++i) {
                int r = brr + i * 16;
                bv[i] = *(const float4*)(B + (size_t)(k0n + r) * NOUT + nBase + bcc);
            }
        }

#pragma unroll
        for (int kk = 0; kk < 32; kk += 8) {
            uint32_t af[2][4], bf[4][2];
#pragma unroll
            for (int mi = 0; mi < 2; ++mi) {
                int rrow = wr * 32 + mi * 16 + g;
                af[mi][0] = As[rrow * 36 + kk + tg];
                af[mi][1] = As[(rrow + 8) * 36 + kk + tg];
                af[mi][2] = As[rrow * 36 + kk + tg + 4];
                af[mi][3] = As[(rrow + 8) * 36 + kk + tg + 4];
            }
#pragma unroll
            for (int ni = 0; ni < 4; ++ni) {
                int col = wc * 32 + ni * 8 + g;
                bf[ni][0] = Bs[(kk + tg) * 68 + col];
                bf[ni][1] = Bs[(kk + tg + 4) * 68 + col];
            }
#pragma unroll
            for (int mi = 0; mi < 2; ++mi)
#pragma unroll
                for (int ni = 0; ni < 4; ++ni) mma8(acc[mi][ni], af[mi], bf[ni]);
        }
    }

    const size_t partBase = (size_t)blockIdx.z * MROWS * NOUT;
#pragma unroll
    for (int mi = 0; mi < 2; ++mi) {
        int r0 = mBase + wr * 32 + mi * 16 + g;
#pragma unroll
        for (int ni = 0; ni < 4; ++ni) {
            int c0 = nBase + wc * 32 + ni * 8 + tg * 2;
            if (r0 < MROWS) {
                g_part[partBase + (size_t)r0 * NOUT + c0]     = acc[mi][ni][0];
                g_part[partBase + (size_t)r0 * NOUT + c0 + 1] = acc[mi][ni][1];
            }
            if (r0 + 8 < MROWS) {
                g_part[partBase + (size_t)(r0 + 8) * NOUT + c0]     = acc[mi][ni][2];
                g_part[partBase + (size_t)(r0 + 8) * NOUT + c0 + 1] = acc[mi][ni][3];
            }
        }
    }
}

// ---------------------------------------------------------------------------
// Epilogue: deterministic split-K reduce + bias + affine LayerNorm(256)
// ---------------------------------------------------------------------------
__global__ void __launch_bounds__(256, 1)
out_ln_kernel(const float* __restrict__ b_out, const float* __restrict__ ln_w,
              const float* __restrict__ ln_b, float* __restrict__ out) {
    __shared__ float red[16];
    const int row = blockIdx.x, t = threadIdx.x;
    float v = b_out[t];
#pragma unroll
    for (int sp = 0; sp < SPLITK; ++sp)
        v += g_part[(size_t)sp * MROWS * NOUT + (size_t)row * NOUT + t];
    float s = v, ss = v * v;
    block_reduce2(s, ss, red, t);
    float mean = s * (1.f / 256.f);
    float inv  = rsqrtf(ss * (1.f / 256.f) - mean * mean + 1e-5f);
    out[(size_t)row * NOUT + t] = (v - mean) * inv * ln_w[t] + ln_b[t];
}

// ---------------------------------------------------------------------------
extern "C" void kernel_launch(void* const* d_in, const int* in_sizes, int n_in,
                              void* d_out, int out_size) {
    (void)in_sizes; (void)n_in; (void)out_size;
    const float* qf      = (const float*)d_in[0];
    const float* sampled = (const float*)d_in[1];
    const float* W_gen   = (const float*)d_in[2];
    const float* b_gen   = (const float*)d_in[3];
    const float* W_out   = (const float*)d_in[4];
    const float* b_out   = (const float*)d_in[5];
    const float* ln_w    = (const float*)d_in[6];
    const float* ln_b    = (const float*)d_in[7];

    gemm1_kernel<<<dim3(N1 / 128, (MROWS + 127) / 128), 256>>>(qf, W_gen, b_gen);
    mid_kernel<<<MROWS, 256>>>(sampled);
    gemm3_kernel<<<dim3(NOUT / 64, (MROWS + 127) / 128, SPLITK), 256>>>(W_out);
    out_ln_kernel<<<MROWS, 256>>>(b_out, ln_w, ln_b, (float*)d_out);
}

// round 8
// speedup vs baseline: 2.4031x; 2.1280x over previous
#include <cuda_runtime.h>
#include <cuda_fp16.h>
#include <math.h>
#include <stdint.h>

// ---------------------------------------------------------------------------
// FeatureMixer, all-fp16 mma.sync.m16n8k16 (fp32 accum), fp32 LN/gelu.
//   params = qf @ W_gen + b_gen        (3600 x 24576, K=256)    fp16 HMMA
//   per (row,h): channel mix+gelu+LN2d, spatial mix+gelu+LN2d   fp16 HMMA
//   out    = mid @ W_out, +b, LN(256)  (3600 x 256, K=16384)    fp16 HMMA splitK
// W_gen pre-transposed to [n][k] with c<->d permutation of the p1 block so the
// channel-mixer weight lands K-major; W_out pre-transposed to [n][k].
// ---------------------------------------------------------------------------

#define DEV __device__ __forceinline__

constexpr int MROWS = 3600;
constexpr int N1    = 24576;
constexpr int K1    = 256;
constexpr int NMID  = 16384;
constexpr int NOUT  = 256;
constexpr int SPLITK = 8;

__device__ __align__(128) __half g_qf_h[(size_t)MROWS * K1];
__device__ __align__(128) __half g_wgenT_h[(size_t)N1 * K1];
__device__ __align__(128) __half g_woutT_h[(size_t)NOUT * NMID];
__device__ __align__(128) float  g_biasP[N1];
__device__ __align__(128) __half g_params_h[(size_t)MROWS * N1];
__device__ __align__(128) __half g_mid_h[(size_t)MROWS * NMID];
__device__ __align__(128) float  g_part[(size_t)SPLITK * MROWS * NOUT];

// ---------------------------------------------------------------------------
DEV uint32_t smem_u32(const void* p) {
    uint32_t a;
    asm("{ .reg .u64 t; cvta.to.shared.u64 t, %1; cvt.u32.u64 %0, t; }"
        : "=r"(a) : "l"(p));
    return a;
}

DEV void mma16(float* c, const uint32_t* a, const uint32_t* b) {
    asm volatile(
        "mma.sync.aligned.m16n8k16.row.col.f32.f16.f16.f32 "
        "{%0,%1,%2,%3}, {%4,%5,%6,%7}, {%8,%9}, {%0,%1,%2,%3};\n"
        : "+f"(c[0]), "+f"(c[1]), "+f"(c[2]), "+f"(c[3])
        : "r"(a[0]), "r"(a[1]), "r"(a[2]), "r"(a[3]), "r"(b[0]), "r"(b[1]));
}

DEV void cp16(uint32_t dst, const void* src, int sz) {
    asm volatile("cp.async.cg.shared.global [%0], [%1], 16, %2;\n"
                 :: "r"(dst), "l"(src), "r"(sz));
}
DEV void cp_commit() { asm volatile("cp.async.commit_group;\n" ::: "memory"); }
DEV void cp_wait1()  { asm volatile("cp.async.wait_group 1;\n" ::: "memory"); }
DEV void cp_wait0()  { asm volatile("cp.async.wait_group 0;\n" ::: "memory"); }

DEV float gelu_exact(float x) {
    return 0.5f * x * (1.0f + erff(x * 0.70710678118654752f));
}

DEV void block_reduce2(float& s, float& ss, float* red, int tid) {
#pragma unroll
    for (int o = 16; o > 0; o >>= 1) {
        s  += __shfl_xor_sync(0xffffffffu, s, o);
        ss += __shfl_xor_sync(0xffffffffu, ss, o);
    }
    if ((tid & 31) == 0) { red[tid >> 5] = s; red[8 + (tid >> 5)] = ss; }
    __syncthreads();
    s = 0.f; ss = 0.f;
#pragma unroll
    for (int i = 0; i < 8; ++i) { s += red[i]; ss += red[8 + i]; }
}

// permutation of param-gen columns: p1 block (n<16384): (h,c,d) -> (h,d,c)
DEV int permn(int n) {
    if (n < 16384) {
        int h = n >> 12, rem = n & 4095, c = rem >> 6, d = rem & 63;
        return (h << 12) + (d << 6) + c;
    }
    return n;
}

// ---------------------------------------------------------------------------
// shared fp16 GEMM mainloop: CTA tile 128x128, BK=32, 2-stage cp.async pipe.
// A[m][k] (guarded rows), Bt[n][k]; 8 warps as 2x4 grid, warp tile 64x32.
// smem per stage: A 128x40 halves + B 128x40 halves (pad 8) = 20480 B.
// ---------------------------------------------------------------------------
DEV void stage_load(uint32_t aB, uint32_t bB,
                    const __half* __restrict__ A, int lda, int mBase,
                    const __half* __restrict__ Bt, int ldb, int nBase,
                    int k0, int t) {
#pragma unroll
    for (int j = 0; j < 2; ++j) {
        int i = t + j * 256, r = i >> 2, c = i & 3;
        int gr = mBase + r;
        const __half* sa = A + (size_t)(gr < MROWS ? gr : 0) * lda + k0 + c * 8;
        cp16(aB + (uint32_t)(r * 80 + c * 16), sa, gr < MROWS ? 16 : 0);
        const __half* sb = Bt + (size_t)(nBase + r) * ldb + k0 + c * 8;
        cp16(bB + (uint32_t)(r * 80 + c * 16), sb, 16);
    }
}

template <int NT>
DEV void mainloop_h(const __half* __restrict__ A, int lda, int mBase,
                    const __half* __restrict__ Bt, int ldb, int nBase,
                    int kStart, __half* sm, float (&acc)[4][4][4], int t) {
    const int lane = t & 31, warp = t >> 5;
    const int g = lane >> 2, tg = lane & 3;
    const int wr = warp >> 2, wc = warp & 3;
    const uint32_t sm32 = smem_u32(sm);

    stage_load(sm32, sm32 + 10240, A, lda, mBase, Bt, ldb, nBase, kStart, t);
    cp_commit();

    for (int kt = 0; kt < NT; ++kt) {
        if (kt + 1 < NT) {
            int s = (kt + 1) & 1;
            stage_load(sm32 + s * 20480, sm32 + s * 20480 + 10240,
                       A, lda, mBase, Bt, ldb, nBase, kStart + (kt + 1) * 32, t);
            cp_commit();
            cp_wait1();
        } else {
            cp_wait0();
        }
        __syncthreads();

        const __half* As = sm + (kt & 1) * 10240;
        const __half* Bs = As + 5120;
#pragma unroll
        for (int kk = 0; kk < 32; kk += 16) {
            uint32_t af[4][4], bf[4][2];
#pragma unroll
            for (int mi = 0; mi < 4; ++mi) {
                int r = wr * 64 + mi * 16 + g;
                af[mi][0] = *(const uint32_t*)(As + r * 40 + kk + 2 * tg);
                af[mi][1] = *(const uint32_t*)(As + (r + 8) * 40 + kk + 2 * tg);
                af[mi][2] = *(const uint32_t*)(As + r * 40 + kk + 2 * tg + 8);
                af[mi][3] = *(const uint32_t*)(As + (r + 8) * 40 + kk + 2 * tg + 8);
            }
#pragma unroll
            for (int ni = 0; ni < 4; ++ni) {
                int n = wc * 32 + ni * 8 + g;
                bf[ni][0] = *(const uint32_t*)(Bs + n * 40 + kk + 2 * tg);
                bf[ni][1] = *(const uint32_t*)(Bs + n * 40 + kk + 2 * tg + 8);
            }
#pragma unroll
            for (int mi = 0; mi < 4; ++mi)
#pragma unroll
                for (int ni = 0; ni < 4; ++ni) mma16(acc[mi][ni], af[mi], bf[ni]);
        }
        __syncthreads();
    }
}

// ---------------------------------------------------------------------------
// GEMM1: g_params_h = qf_h @ wgenT_h^T + biasP   grid(192,29)
// ---------------------------------------------------------------------------
__global__ void __launch_bounds__(256, 2)
gemm1_h_kernel() {
    __shared__ __align__(16) __half sm[2 * 10240];
    const int t = threadIdx.x, lane = t & 31, warp = t >> 5;
    const int g = lane >> 2, tg = lane & 3;
    const int wr = warp >> 2, wc = warp & 3;
    const int mBase = blockIdx.y * 128, nBase = blockIdx.x * 128;

    float acc[4][4][4];
#pragma unroll
    for (int i = 0; i < 4; ++i)
#pragma unroll
        for (int j = 0; j < 4; ++j)
#pragma unroll
            for (int k = 0; k < 4; ++k) acc[i][j][k] = 0.f;

    mainloop_h<8>(g_qf_h, K1, mBase, g_wgenT_h, K1, nBase, 0, sm, acc, t);

#pragma unroll
    for (int mi = 0; mi < 4; ++mi) {
        int r0 = mBase + wr * 64 + mi * 16 + g;
#pragma unroll
        for (int ni = 0; ni < 4; ++ni) {
            int c0 = nBase + wc * 32 + ni * 8 + tg * 2;
            float b0 = g_biasP[c0], b1 = g_biasP[c0 + 1];
            if (r0 < MROWS)
                *(__half2*)(g_params_h + (size_t)r0 * N1 + c0) =
                    __floats2half2_rn(acc[mi][ni][0] + b0, acc[mi][ni][1] + b1);
            if (r0 + 8 < MROWS)
                *(__half2*)(g_params_h + (size_t)(r0 + 8) * N1 + c0) =
                    __floats2half2_rn(acc[mi][ni][2] + b0, acc[mi][ni][3] + b1);
        }
    }
}

// ---------------------------------------------------------------------------
// GEMM3: g_part[z] = g_mid_h @ woutT_h^T    grid(2,29,8)
// ---------------------------------------------------------------------------
__global__ void __launch_bounds__(256, 2)
gemm3_h_kernel() {
    __shared__ __align__(16) __half sm[2 * 10240];
    const int t = threadIdx.x, lane = t & 31, warp = t >> 5;
    const int g = lane >> 2, tg = lane & 3;
    const int wr = warp >> 2, wc = warp & 3;
    const int mBase = blockIdx.y * 128, nBase = blockIdx.x * 128;
    const int kStart = blockIdx.z * (NMID / SPLITK);

    float acc[4][4][4];
#pragma unroll
    for (int i = 0; i < 4; ++i)
#pragma unroll
        for (int j = 0; j < 4; ++j)
#pragma unroll
            for (int k = 0; k < 4; ++k) acc[i][j][k] = 0.f;

    mainloop_h<(NMID / SPLITK) / 32>(g_mid_h, NMID, mBase, g_woutT_h, NMID, nBase,
                                     kStart, sm, acc, t);

    float* pbase = g_part + (size_t)blockIdx.z * MROWS * NOUT;
#pragma unroll
    for (int mi = 0; mi < 4; ++mi) {
        int r0 = mBase + wr * 64 + mi * 16 + g;
#pragma unroll
        for (int ni = 0; ni < 4; ++ni) {
            int c0 = nBase + wc * 32 + ni * 8 + tg * 2;
            if (r0 < MROWS) {
                pbase[(size_t)r0 * NOUT + c0]     = acc[mi][ni][0];
                pbase[(size_t)r0 * NOUT + c0 + 1] = acc[mi][ni][1];
            }
            if (r0 + 8 < MROWS) {
                pbase[(size_t)(r0 + 8) * NOUT + c0]     = acc[mi][ni][2];
                pbase[(size_t)(r0 + 8) * NOUT + c0 + 1] = acc[mi][ni][3];
            }
        }
    }
}

// ---------------------------------------------------------------------------
// Mid kernel (fp16 HMMA): one CTA per (b,q) row.
// Stage A per head: O1(32p x 64d) = S(32x64c) @ P1t(64d x 64c)^T; gelu; LN2048
// Stage B per head: O2(64e x 64d) = P2(64x32p) @ O1t(64d x 32p)^T; gelu; LN4096
// ---------------------------------------------------------------------------
__global__ void __launch_bounds__(256, 3)
mid_h_kernel(const float* __restrict__ sampled) {
    __shared__ __align__(16) __half sP1[64 * 72];  // [d][c]
    __shared__ __align__(16) __half sS[32 * 72];   // [p][c]
    __shared__ __align__(16) __half sP2[64 * 40];  // [e][p]
    __shared__ __align__(16) __half sO1[64 * 40];  // [d][p] (normalized O1)
    __shared__ float red[16];

    const int row = blockIdx.x, t = threadIdx.x;
    const int lane = t & 31, warp = t >> 5;
    const int g = lane >> 2, tg = lane & 3;
    const __half* prow = g_params_h + (size_t)row * N1;
    const float* srow = sampled + (size_t)row * 8192;
    __half* mrow = g_mid_h + (size_t)row * NMID;

    const int wr = warp & 1, wc = warp >> 1;   // A: 2x4 (16p x 16d); B: 2x4 (32e x 16d)

    for (int h = 0; h < 4; ++h) {
        __syncthreads();
        // P1t: 4096 halves
#pragma unroll
        for (int j = 0; j < 2; ++j) {
            int i = t + j * 256, d = i >> 3, c8 = i & 7;
            *(uint4*)(sP1 + d * 72 + c8 * 8) =
                *(const uint4*)(prow + h * 4096 + d * 64 + c8 * 8);
        }
        // S: 32x64 fp32 -> fp16
#pragma unroll
        for (int j = 0; j < 2; ++j) {
            int i = t + j * 256, p = i >> 4, c4 = i & 15;
            float4 v = *(const float4*)(srow + h * 2048 + p * 64 + c4 * 4);
            __half2 ha = __floats2half2_rn(v.x, v.y);
            __half2 hb = __floats2half2_rn(v.z, v.w);
            *(uint2*)(sS + p * 72 + c4 * 4) =
                make_uint2(*(uint32_t*)&ha, *(uint32_t*)&hb);
        }
        // P2: 2048 halves
        {
            int e = t >> 2, p8 = t & 3;
            *(uint4*)(sP2 + e * 40 + p8 * 8) =
                *(const uint4*)(prow + 16384 + h * 2048 + e * 32 + p8 * 8);
        }
        __syncthreads();

        // ---- stage A: M=32(p) N=64(d) K=64(c) ----
        float accA[2][4];
#pragma unroll
        for (int i = 0; i < 2; ++i)
#pragma unroll
            for (int j = 0; j < 4; ++j) accA[i][j] = 0.f;

        const int p0 = wr * 16 + g;
#pragma unroll
        for (int kk = 0; kk < 64; kk += 16) {
            uint32_t a[4];
            a[0] = *(const uint32_t*)(sS + p0 * 72 + kk + 2 * tg);
            a[1] = *(const uint32_t*)(sS + (p0 + 8) * 72 + kk + 2 * tg);
            a[2] = *(const uint32_t*)(sS + p0 * 72 + kk + 2 * tg + 8);
            a[3] = *(const uint32_t*)(sS + (p0 + 8) * 72 + kk + 2 * tg + 8);
#pragma unroll
            for (int ni = 0; ni < 2; ++ni) {
                int nd = wc * 16 + ni * 8 + g;
                uint32_t b[2];
                b[0] = *(const uint32_t*)(sP1 + nd * 72 + kk + 2 * tg);
                b[1] = *(const uint32_t*)(sP1 + nd * 72 + kk + 2 * tg + 8);
                mma16(accA[ni], a, b);
            }
        }

        float s = 0.f, ss = 0.f;
#pragma unroll
        for (int i = 0; i < 2; ++i)
#pragma unroll
            for (int j = 0; j < 4; ++j) {
                accA[i][j] = gelu_exact(accA[i][j]);
                s += accA[i][j]; ss += accA[i][j] * accA[i][j];
            }
        block_reduce2(s, ss, red, t);
        float mean = s * (1.f / 2048.f);
        float inv  = rsqrtf(ss * (1.f / 2048.f) - mean * mean + 1e-5f);
#pragma unroll
        for (int ni = 0; ni < 2; ++ni) {
            int d0 = wc * 16 + ni * 8 + 2 * tg;
            sO1[d0 * 40 + p0]           = __float2half_rn((accA[ni][0] - mean) * inv);
            sO1[(d0 + 1) * 40 + p0]     = __float2half_rn((accA[ni][1] - mean) * inv);
            sO1[d0 * 40 + p0 + 8]       = __float2half_rn((accA[ni][2] - mean) * inv);
            sO1[(d0 + 1) * 40 + p0 + 8] = __float2half_rn((accA[ni][3] - mean) * inv);
        }
        __syncthreads();

        // ---- stage B: M=64(e) N=64(d) K=32(p) ----
        float accB[2][2][4];
#pragma unroll
        for (int i = 0; i < 2; ++i)
#pragma unroll
            for (int j = 0; j < 2; ++j)
#pragma unroll
                for (int k = 0; k < 4; ++k) accB[i][j][k] = 0.f;

#pragma unroll
        for (int kk = 0; kk < 32; kk += 16) {
            uint32_t a[2][4];
#pragma unroll
            for (int mi = 0; mi < 2; ++mi) {
                int e0 = wr * 32 + mi * 16 + g;
                a[mi][0] = *(const uint32_t*)(sP2 + e0 * 40 + kk + 2 * tg);
                a[mi][1] = *(const uint32_t*)(sP2 + (e0 + 8) * 40 + kk + 2 * tg);
                a[mi][2] = *(const uint32_t*)(sP2 + e0 * 40 + kk + 2 * tg + 8);
                a[mi][3] = *(const uint32_t*)(sP2 + (e0 + 8) * 40 + kk + 2 * tg + 8);
            }
#pragma unroll
            for (int ni = 0; ni < 2; ++ni) {
                int nd = wc * 16 + ni * 8 + g;
                uint32_t b[2];
                b[0] = *(const uint32_t*)(sO1 + nd * 40 + kk + 2 * tg);
                b[1] = *(const uint32_t*)(sO1 + nd * 40 + kk + 2 * tg + 8);
#pragma unroll
                for (int mi = 0; mi < 2; ++mi) mma16(accB[mi][ni], a[mi], b);
            }
        }

        s = 0.f; ss = 0.f;
#pragma unroll
        for (int i = 0; i < 2; ++i)
#pragma unroll
            for (int j = 0; j < 2; ++j)
#pragma unroll
                for (int k = 0; k < 4; ++k) {
                    accB[i][j][k] = gelu_exact(accB[i][j][k]);
                    s += accB[i][j][k]; ss += accB[i][j][k] * accB[i][j][k];
                }
        block_reduce2(s, ss, red, t);
        mean = s * (1.f / 4096.f);
        inv  = rsqrtf(ss * (1.f / 4096.f) - mean * mean + 1e-5f);
        __half* hrow = mrow + h * 4096;
#pragma unroll
        for (int mi = 0; mi < 2; ++mi) {
            int e0 = wr * 32 + mi * 16 + g;
#pragma unroll
            for (int ni = 0; ni < 2; ++ni) {
                int c0 = wc * 16 + ni * 8 + 2 * tg;
                *(__half2*)(hrow + e0 * 64 + c0) =
                    __floats2half2_rn((accB[mi][ni][0] - mean) * inv,
                                      (accB[mi][ni][1] - mean) * inv);
                *(__half2*)(hrow + (e0 + 8) * 64 + c0) =
                    __floats2half2_rn((accB[mi][ni][2] - mean) * inv,
                                      (accB[mi][ni][3] - mean) * inv);
            }
        }
    }
}

// ---------------------------------------------------------------------------
// conversions
// ---------------------------------------------------------------------------
__global__ void __launch_bounds__(256)
cvt_qf_kernel(const float* __restrict__ in) {
    int i = blockIdx.x * 256 + threadIdx.x;          // 230400 float4 chunks
    float4 v = *(const float4*)(in + (size_t)i * 4);
    __half2 ha = __floats2half2_rn(v.x, v.y);
    __half2 hb = __floats2half2_rn(v.z, v.w);
    *(uint2*)(g_qf_h + (size_t)i * 4) = make_uint2(*(uint32_t*)&ha, *(uint32_t*)&hb);
}

// W_gen fp32 [256][24576] -> g_wgenT_h [perm(n)][256] half
__global__ void __launch_bounds__(256)
cvt_wgen_kernel(const float* __restrict__ in) {
    __shared__ float tile[32][33];
    const int n0 = blockIdx.x * 32, k0 = blockIdx.y * 32;
    const int tx = threadIdx.x, ty = threadIdx.y;
#pragma unroll
    for (int j = 0; j < 32; j += 8)
        tile[ty + j][tx] = in[(size_t)(k0 + ty + j) * N1 + n0 + tx];
    __syncthreads();
#pragma unroll
    for (int j = 0; j < 32; j += 8) {
        int np = permn(n0 + ty + j);
        g_wgenT_h[(size_t)np * K1 + k0 + tx] = __float2half_rn(tile[tx][ty + j]);
    }
}

// W_out fp32 [16384][256] -> g_woutT_h [256][16384] half
__global__ void __launch_bounds__(256)
cvt_wout_kernel(const float* __restrict__ in) {
    __shared__ float tile[32][33];
    const int n0 = blockIdx.x * 32, k0 = blockIdx.y * 32;
    const int tx = threadIdx.x, ty = threadIdx.y;
#pragma unroll
    for (int j = 0; j < 32; j += 8)
        tile[ty + j][tx] = in[(size_t)(k0 + ty + j) * NOUT + n0 + tx];
    __syncthreads();
#pragma unroll
    for (int j = 0; j < 32; j += 8)
        g_woutT_h[(size_t)(n0 + ty + j) * NMID + k0 + tx] = __float2half_rn(tile[tx][ty + j]);
}

__global__ void __launch_bounds__(256)
cvt_bias_kernel(const float* __restrict__ b_gen) {
    int n = blockIdx.x * 256 + threadIdx.x;
    g_biasP[permn(n)] = b_gen[n];
}

// ---------------------------------------------------------------------------
// Epilogue: deterministic split-K reduce + bias + affine LayerNorm(256)
// ---------------------------------------------------------------------------
__global__ void __launch_bounds__(256, 1)
out_ln_kernel(const float* __restrict__ b_out, const float* __restrict__ ln_w,
              const float* __restrict__ ln_b, float* __restrict__ out) {
    __shared__ float red[16];
    const int row = blockIdx.x, t = threadIdx.x;
    float v = b_out[t];
#pragma unroll
    for (int sp = 0; sp < SPLITK; ++sp)
        v += g_part[(size_t)sp * MROWS * NOUT + (size_t)row * NOUT + t];
    float s = v, ss = v * v;
    block_reduce2(s, ss, red, t);
    float mean = s * (1.f / 256.f);
    float inv  = rsqrtf(ss * (1.f / 256.f) - mean * mean + 1e-5f);
    out[(size_t)row * NOUT + t] = (v - mean) * inv * ln_w[t] + ln_b[t];
}

// ---------------------------------------------------------------------------
extern "C" void kernel_launch(void* const* d_in, const int* in_sizes, int n_in,
                              void* d_out, int out_size) {
    (void)in_sizes; (void)n_in; (void)out_size;
    const float* qf      = (const float*)d_in[0];
    const float* sampled = (const float*)d_in[1];
    const float* W_gen   = (const float*)d_in[2];
    const float* b_gen   = (const float*)d_in[3];
    const float* W_out   = (const float*)d_in[4];
    const float* b_out   = (const float*)d_in[5];
    const float* ln_w    = (const float*)d_in[6];
    const float* ln_b    = (const float*)d_in[7];

    cvt_qf_kernel<<<(MROWS * K1 / 4) / 256, 256>>>(qf);
    cvt_wgen_kernel<<<dim3(N1 / 32, K1 / 32), dim3(32, 8)>>>(W_gen);
    cvt_wout_kernel<<<dim3(NOUT / 32, NMID / 32), dim3(32, 8)>>>(W_out);
    cvt_bias_kernel<<<N1 / 256, 256>>>(b_gen);

    gemm1_h_kernel<<<dim3(N1 / 128, (MROWS + 127) / 128), 256>>>();
    mid_h_kernel<<<MROWS, 256>>>(sampled);
    gemm3_h_kernel<<<dim3(NOUT / 128, (MROWS + 127) / 128, SPLITK), 256>>>();
    out_ln_kernel<<<MROWS, 256>>>(b_out, ln_w, ln_b, (float*)d_out);
}

// round 10
// speedup vs baseline: 2.7418x; 1.1410x over previous
#include <cuda_runtime.h>
#include <cuda_fp16.h>
#include <math.h>
#include <stdint.h>

// ---------------------------------------------------------------------------
// FeatureMixer, all-fp16 mma.sync.m16n8k16 (fp32 accum), fp32 LN/gelu.
//   params = qf @ W_gen + b_gen        (3600 x 24576, K=256)    fp16 HMMA
//   per (row,h): channel mix+gelu+LN2d, spatial mix+gelu+LN2d   fp16 HMMA
//   out    = mid @ W_out, +b, LN(256)  (3600 x 256, K=16384)    fp16 HMMA splitK
// R9b: ldmatrix fragment loads, 3-stage cp.async pipeline (1 sync/ktile),
//      GEMM3 split-K 16. (fixes R9 shadowing compile error)
// ---------------------------------------------------------------------------

#define DEV __device__ __forceinline__

constexpr int MROWS = 3600;
constexpr int N1    = 24576;
constexpr int K1    = 256;
constexpr int NMID  = 16384;
constexpr int NOUT  = 256;
constexpr int SPLITK = 16;

constexpr int STAGE_BYTES = 20480;           // A 10240 + B 10240
constexpr int SMEM_BYTES  = 3 * STAGE_BYTES; // 61440

__device__ __align__(128) __half g_qf_h[(size_t)MROWS * K1];
__device__ __align__(128) __half g_wgenT_h[(size_t)N1 * K1];
__device__ __align__(128) __half g_woutT_h[(size_t)NOUT * NMID];
__device__ __align__(128) float  g_biasP[N1];
__device__ __align__(128) __half g_params_h[(size_t)MROWS * N1];
__device__ __align__(128) __half g_mid_h[(size_t)MROWS * NMID];
__device__ __align__(128) float  g_part[(size_t)SPLITK * MROWS * NOUT];

// ---------------------------------------------------------------------------
DEV uint32_t smem_u32(const void* p) {
    uint32_t a;
    asm("{ .reg .u64 t; cvta.to.shared.u64 t, %1; cvt.u32.u64 %0, t; }"
        : "=r"(a) : "l"(p));
    return a;
}

DEV void mma16(float* c, const uint32_t* a, const uint32_t* b) {
    asm volatile(
        "mma.sync.aligned.m16n8k16.row.col.f32.f16.f16.f32 "
        "{%0,%1,%2,%3}, {%4,%5,%6,%7}, {%8,%9}, {%0,%1,%2,%3};\n"
        : "+f"(c[0]), "+f"(c[1]), "+f"(c[2]), "+f"(c[3])
        : "r"(a[0]), "r"(a[1]), "r"(a[2]), "r"(a[3]), "r"(b[0]), "r"(b[1]));
}

DEV void ldsm4(uint32_t& r0, uint32_t& r1, uint32_t& r2, uint32_t& r3,
               uint32_t addr) {
    asm volatile(
        "ldmatrix.sync.aligned.m8n8.x4.shared.b16 {%0,%1,%2,%3}, [%4];"
        : "=r"(r0), "=r"(r1), "=r"(r2), "=r"(r3) : "r"(addr));
}

DEV void cp16(uint32_t dst, const void* src, int sz) {
    asm volatile("cp.async.cg.shared.global [%0], [%1], 16, %2;\n"
                 :: "r"(dst), "l"(src), "r"(sz));
}
DEV void cp_commit() { asm volatile("cp.async.commit_group;\n" ::: "memory"); }
DEV void cp_wait1()  { asm volatile("cp.async.wait_group 1;\n" ::: "memory"); }

DEV float gelu_exact(float x) {
    return 0.5f * x * (1.0f + erff(x * 0.70710678118654752f));
}

DEV void block_reduce2(float& s, float& ss, float* red, int tid) {
#pragma unroll
    for (int o = 16; o > 0; o >>= 1) {
        s  += __shfl_xor_sync(0xffffffffu, s, o);
        ss += __shfl_xor_sync(0xffffffffu, ss, o);
    }
    if ((tid & 31) == 0) { red[tid >> 5] = s; red[8 + (tid >> 5)] = ss; }
    __syncthreads();
    s = 0.f; ss = 0.f;
#pragma unroll
    for (int i = 0; i < 8; ++i) { s += red[i]; ss += red[8 + i]; }
}

// permutation of param-gen columns: p1 block (n<16384): (h,c,d) -> (h,d,c)
DEV int permn(int n) {
    if (n < 16384) {
        int h = n >> 12, rem = n & 4095, c = rem >> 6, d = rem & 63;
        return (h << 12) + (d << 6) + c;
    }
    return n;
}

// ---------------------------------------------------------------------------
// fp16 GEMM mainloop: CTA tile 128x128, BK=32, 3-stage cp.async pipeline.
// A[m][k] (guarded rows), Bt[n][k]; 8 warps as 2x4 grid, warp tile 64x32.
// smem per stage: A 128 rows x 80B + B 128 rows x 80B (first 64B live).
// ---------------------------------------------------------------------------
DEV void stage_load(uint32_t sbase,
                    const __half* __restrict__ A, int lda, int mBase,
                    const __half* __restrict__ Bt, int ldb, int nBase,
                    int k0, int t) {
#pragma unroll
    for (int j = 0; j < 2; ++j) {
        int i = t + j * 256, r = i >> 2, c = i & 3;
        int gr = mBase + r;
        const __half* sa = A + (size_t)(gr < MROWS ? gr : 0) * lda + k0 + c * 8;
        cp16(sbase + (uint32_t)(r * 80 + c * 16), sa, gr < MROWS ? 16 : 0);
        const __half* sb = Bt + (size_t)(nBase + r) * ldb + k0 + c * 8;
        cp16(sbase + 10240u + (uint32_t)(r * 80 + c * 16), sb, 16);
    }
}

template <int NT>
DEV void mainloop_h(const __half* __restrict__ A, int lda, int mBase,
                    const __half* __restrict__ Bt, int ldb, int nBase,
                    int kStart, uint32_t sm32, float (&acc)[4][4][4], int t) {
    const int lane = t & 31, warp = t >> 5;
    const int wr = warp >> 2, wc = warp & 3;
    const int sub = lane & 7;

    // ldmatrix per-lane address components
    const int aRow = ((lane >> 3) & 1) * 8 + sub;   // row offset within 16
    const int aK   = (lane >> 4) * 8;               // k offset (0/8)
    const int bRow = (lane >> 4) * 8 + sub;         // row offset (2 n-tiles)
    const int bK   = ((lane >> 3) & 1) * 8;

    stage_load(sm32, A, lda, mBase, Bt, ldb, nBase, kStart, t);
    cp_commit();
    stage_load(sm32 + STAGE_BYTES, A, lda, mBase, Bt, ldb, nBase, kStart + 32, t);
    cp_commit();

    for (int kt = 0; kt < NT; ++kt) {
        cp_wait1();
        __syncthreads();

        const uint32_t aB = sm32 + (uint32_t)((kt % 3) * STAGE_BYTES);
        const uint32_t bB = aB + 10240u;

#pragma unroll
        for (int kk = 0; kk < 32; kk += 16) {
            uint32_t af[4][4], bf[4][2];
#pragma unroll
            for (int mi = 0; mi < 4; ++mi) {
                int r = wr * 64 + mi * 16 + aRow;
                ldsm4(af[mi][0], af[mi][1], af[mi][2], af[mi][3],
                      aB + (uint32_t)(r * 80 + (kk + aK) * 2));
            }
#pragma unroll
            for (int n2 = 0; n2 < 2; ++n2) {
                int n = wc * 32 + n2 * 16 + bRow;
                ldsm4(bf[n2 * 2][0], bf[n2 * 2][1], bf[n2 * 2 + 1][0],
                      bf[n2 * 2 + 1][1],
                      bB + (uint32_t)(n * 80 + (kk + bK) * 2));
            }
#pragma unroll
            for (int mi = 0; mi < 4; ++mi)
#pragma unroll
                for (int ni = 0; ni < 4; ++ni) mma16(acc[mi][ni], af[mi], bf[ni]);
        }

        // prefetch kt+2 into stage (kt+2)%3 (safe: all warps passed this
        // iteration's sync, so stage (kt-1)%3 reads are complete)
        if (kt + 2 < NT)
            stage_load(sm32 + (uint32_t)(((kt + 2) % 3) * STAGE_BYTES),
                       A, lda, mBase, Bt, ldb, nBase, kStart + (kt + 2) * 32, t);
        cp_commit();
    }
}

// ---------------------------------------------------------------------------
// GEMM1: g_params_h = qf_h @ wgenT_h^T + biasP   grid(192,29)
// ---------------------------------------------------------------------------
__global__ void __launch_bounds__(256, 2)
gemm1_h_kernel() {
    extern __shared__ __align__(128) __half smem_dyn[];
    const int t = threadIdx.x, lane = t & 31, warp = t >> 5;
    const int g = lane >> 2, tg = lane & 3;
    const int wr = warp >> 2, wc = warp & 3;
    const int mBase = blockIdx.y * 128, nBase = blockIdx.x * 128;

    float acc[4][4][4];
#pragma unroll
    for (int i = 0; i < 4; ++i)
#pragma unroll
        for (int j = 0; j < 4; ++j)
#pragma unroll
            for (int k = 0; k < 4; ++k) acc[i][j][k] = 0.f;

    mainloop_h<8>(g_qf_h, K1, mBase, g_wgenT_h, K1, nBase, 0,
                  smem_u32(smem_dyn), acc, t);

#pragma unroll
    for (int mi = 0; mi < 4; ++mi) {
        int r0 = mBase + wr * 64 + mi * 16 + g;
#pragma unroll
        for (int ni = 0; ni < 4; ++ni) {
            int c0 = nBase + wc * 32 + ni * 8 + tg * 2;
            float b0 = g_biasP[c0], b1 = g_biasP[c0 + 1];
            if (r0 < MROWS)
                *(__half2*)(g_params_h + (size_t)r0 * N1 + c0) =
                    __floats2half2_rn(acc[mi][ni][0] + b0, acc[mi][ni][1] + b1);
            if (r0 + 8 < MROWS)
                *(__half2*)(g_params_h + (size_t)(r0 + 8) * N1 + c0) =
                    __floats2half2_rn(acc[mi][ni][2] + b0, acc[mi][ni][3] + b1);
        }
    }
}

// ---------------------------------------------------------------------------
// GEMM3: g_part[z] = g_mid_h @ woutT_h^T    grid(2,29,16)
// ---------------------------------------------------------------------------
__global__ void __launch_bounds__(256, 2)
gemm3_h_kernel() {
    extern __shared__ __align__(128) __half smem_dyn[];
    const int t = threadIdx.x, lane = t & 31, warp = t >> 5;
    const int g = lane >> 2, tg = lane & 3;
    const int wr = warp >> 2, wc = warp & 3;
    const int mBase = blockIdx.y * 128, nBase = blockIdx.x * 128;
    const int kStart = blockIdx.z * (NMID / SPLITK);

    float acc[4][4][4];
#pragma unroll
    for (int i = 0; i < 4; ++i)
#pragma unroll
        for (int j = 0; j < 4; ++j)
#pragma unroll
            for (int k = 0; k < 4; ++k) acc[i][j][k] = 0.f;

    mainloop_h<(NMID / SPLITK) / 32>(g_mid_h, NMID, mBase, g_woutT_h, NMID,
                                     nBase, kStart, smem_u32(smem_dyn), acc, t);

    float* pbase = g_part + (size_t)blockIdx.z * MROWS * NOUT;
#pragma unroll
    for (int mi = 0; mi < 4; ++mi) {
        int r0 = mBase + wr * 64 + mi * 16 + g;
#pragma unroll
        for (int ni = 0; ni < 4; ++ni) {
            int c0 = nBase + wc * 32 + ni * 8 + tg * 2;
            if (r0 < MROWS) {
                pbase[(size_t)r0 * NOUT + c0]     = acc[mi][ni][0];
                pbase[(size_t)r0 * NOUT + c0 + 1] = acc[mi][ni][1];
            }
            if (r0 + 8 < MROWS) {
                pbase[(size_t)(r0 + 8) * NOUT + c0]     = acc[mi][ni][2];
                pbase[(size_t)(r0 + 8) * NOUT + c0 + 1] = acc[mi][ni][3];
            }
        }
    }
}

// ---------------------------------------------------------------------------
// Mid kernel (fp16 HMMA): one CTA per (b,q) row.
// ---------------------------------------------------------------------------
__global__ void __launch_bounds__(256, 3)
mid_h_kernel(const float* __restrict__ sampled) {
    __shared__ __align__(16) __half sP1[64 * 72];  // [d][c]
    __shared__ __align__(16) __half sS[32 * 72];   // [p][c]
    __shared__ __align__(16) __half sP2[64 * 40];  // [e][p]
    __shared__ __align__(16) __half sO1[64 * 40];  // [d][p]
    __shared__ float red[16];

    const int row = blockIdx.x, t = threadIdx.x;
    const int lane = t & 31, warp = t >> 5;
    const int g = lane >> 2, tg = lane & 3;
    const __half* prow = g_params_h + (size_t)row * N1;
    const float* srow = sampled + (size_t)row * 8192;
    __half* mrow = g_mid_h + (size_t)row * NMID;

    const int wr = warp & 1, wc = warp >> 1;

    for (int h = 0; h < 4; ++h) {
        __syncthreads();
#pragma unroll
        for (int j = 0; j < 2; ++j) {
            int i = t + j * 256, d = i >> 3, c8 = i & 7;
            *(uint4*)(sP1 + d * 72 + c8 * 8) =
                *(const uint4*)(prow + h * 4096 + d * 64 + c8 * 8);
        }
#pragma unroll
        for (int j = 0; j < 2; ++j) {
            int i = t + j * 256, p = i >> 4, c4 = i & 15;
            float4 v = *(const float4*)(srow + h * 2048 + p * 64 + c4 * 4);
            __half2 ha = __floats2half2_rn(v.x, v.y);
            __half2 hb = __floats2half2_rn(v.z, v.w);
            *(uint2*)(sS + p * 72 + c4 * 4) =
                make_uint2(*(uint32_t*)&ha, *(uint32_t*)&hb);
        }
        {
            int e = t >> 2, p8 = t & 3;
            *(uint4*)(sP2 + e * 40 + p8 * 8) =
                *(const uint4*)(prow + 16384 + h * 2048 + e * 32 + p8 * 8);
        }
        __syncthreads();

        // ---- stage A: M=32(p) N=64(d) K=64(c) ----
        float accA[2][4];
#pragma unroll
        for (int i = 0; i < 2; ++i)
#pragma unroll
            for (int j = 0; j < 4; ++j) accA[i][j] = 0.f;

        const int p0 = wr * 16 + g;
#pragma unroll
        for (int kk = 0; kk < 64; kk += 16) {
            uint32_t a[4];
            a[0] = *(const uint32_t*)(sS + p0 * 72 + kk + 2 * tg);
            a[1] = *(const uint32_t*)(sS + (p0 + 8) * 72 + kk + 2 * tg);
            a[2] = *(const uint32_t*)(sS + p0 * 72 + kk + 2 * tg + 8);
            a[3] = *(const uint32_t*)(sS + (p0 + 8) * 72 + kk + 2 * tg + 8);
#pragma unroll
            for (int ni = 0; ni < 2; ++ni) {
                int nd = wc * 16 + ni * 8 + g;
                uint32_t b[2];
                b[0] = *(const uint32_t*)(sP1 + nd * 72 + kk + 2 * tg);
                b[1] = *(const uint32_t*)(sP1 + nd * 72 + kk + 2 * tg + 8);
                mma16(accA[ni], a, b);
            }
        }

        float s = 0.f, ss = 0.f;
#pragma unroll
        for (int i = 0; i < 2; ++i)
#pragma unroll
            for (int j = 0; j < 4; ++j) {
                accA[i][j] = gelu_exact(accA[i][j]);
                s += accA[i][j]; ss += accA[i][j] * accA[i][j];
            }
        block_reduce2(s, ss, red, t);
        float mean = s * (1.f / 2048.f);
        float inv  = rsqrtf(ss * (1.f / 2048.f) - mean * mean + 1e-5f);
#pragma unroll
        for (int ni = 0; ni < 2; ++ni) {
            int d0 = wc * 16 + ni * 8 + 2 * tg;
            sO1[d0 * 40 + p0]           = __float2half_rn((accA[ni][0] - mean) * inv);
            sO1[(d0 + 1) * 40 + p0]     = __float2half_rn((accA[ni][1] - mean) * inv);
            sO1[d0 * 40 + p0 + 8]       = __float2half_rn((accA[ni][2] - mean) * inv);
            sO1[(d0 + 1) * 40 + p0 + 8] = __float2half_rn((accA[ni][3] - mean) * inv);
        }
        __syncthreads();

        // ---- stage B: M=64(e) N=64(d) K=32(p) ----
        float accB[2][2][4];
#pragma unroll
        for (int i = 0; i < 2; ++i)
#pragma unroll
            for (int j = 0; j < 2; ++j)
#pragma unroll
                for (int k = 0; k < 4; ++k) accB[i][j][k] = 0.f;

#pragma unroll
        for (int kk = 0; kk < 32; kk += 16) {
            uint32_t a[2][4];
#pragma unroll
            for (int mi = 0; mi < 2; ++mi) {
                int e0 = wr * 32 + mi * 16 + g;
                a[mi][0] = *(const uint32_t*)(sP2 + e0 * 40 + kk + 2 * tg);
                a[mi][1] = *(const uint32_t*)(sP2 + (e0 + 8) * 40 + kk + 2 * tg);
                a[mi][2] = *(const uint32_t*)(sP2 + e0 * 40 + kk + 2 * tg + 8);
                a[mi][3] = *(const uint32_t*)(sP2 + (e0 + 8) * 40 + kk + 2 * tg + 8);
            }
#pragma unroll
            for (int ni = 0; ni < 2; ++ni) {
                int nd = wc * 16 + ni * 8 + g;
                uint32_t b[2];
                b[0] = *(const uint32_t*)(sO1 + nd * 40 + kk + 2 * tg);
                b[1] = *(const uint32_t*)(sO1 + nd * 40 + kk + 2 * tg + 8);
#pragma unroll
                for (int mi = 0; mi < 2; ++mi) mma16(accB[mi][ni], a[mi], b);
            }
        }

        s = 0.f; ss = 0.f;
#pragma unroll
        for (int i = 0; i < 2; ++i)
#pragma unroll
            for (int j = 0; j < 2; ++j)
#pragma unroll
                for (int k = 0; k < 4; ++k) {
                    accB[i][j][k] = gelu_exact(accB[i][j][k]);
                    s += accB[i][j][k]; ss += accB[i][j][k] * accB[i][j][k];
                }
        block_reduce2(s, ss, red, t);
        mean = s * (1.f / 4096.f);
        inv  = rsqrtf(ss * (1.f / 4096.f) - mean * mean + 1e-5f);
        __half* hrow = mrow + h * 4096;
#pragma unroll
        for (int mi = 0; mi < 2; ++mi) {
            int e0 = wr * 32 + mi * 16 + g;
#pragma unroll
            for (int ni = 0; ni < 2; ++ni) {
                int c0 = wc * 16 + ni * 8 + 2 * tg;
                *(__half2*)(hrow + e0 * 64 + c0) =
                    __floats2half2_rn((accB[mi][ni][0] - mean) * inv,
                                      (accB[mi][ni][1] - mean) * inv);
                *(__half2*)(hrow + (e0 + 8) * 64 + c0) =
                    __floats2half2_rn((accB[mi][ni][2] - mean) * inv,
                                      (accB[mi][ni][3] - mean) * inv);
            }
        }
    }
}

// ---------------------------------------------------------------------------
// conversions
// ---------------------------------------------------------------------------
__global__ void __launch_bounds__(256)
cvt_qf_kernel(const float* __restrict__ in) {
    int i = blockIdx.x * 256 + threadIdx.x;
    float4 v = *(const float4*)(in + (size_t)i * 4);
    __half2 ha = __floats2half2_rn(v.x, v.y);
    __half2 hb = __floats2half2_rn(v.z, v.w);
    *(uint2*)(g_qf_h + (size_t)i * 4) = make_uint2(*(uint32_t*)&ha, *(uint32_t*)&hb);
}

__global__ void __launch_bounds__(256)
cvt_wgen_kernel(const float* __restrict__ in) {
    __shared__ float tile[32][33];
    const int n0 = blockIdx.x * 32, k0 = blockIdx.y * 32;
    const int tx = threadIdx.x, ty = threadIdx.y;
#pragma unroll
    for (int j = 0; j < 32; j += 8)
        tile[ty + j][tx] = in[(size_t)(k0 + ty + j) * N1 + n0 + tx];
    __syncthreads();
#pragma unroll
    for (int j = 0; j < 32; j += 8) {
        int np = permn(n0 + ty + j);
        g_wgenT_h[(size_t)np * K1 + k0 + tx] = __float2half_rn(tile[tx][ty + j]);
    }
}

__global__ void __launch_bounds__(256)
cvt_wout_kernel(const float* __restrict__ in) {
    __shared__ float tile[32][33];
    const int n0 = blockIdx.x * 32, k0 = blockIdx.y * 32;
    const int tx = threadIdx.x, ty = threadIdx.y;
#pragma unroll
    for (int j = 0; j < 32; j += 8)
        tile[ty + j][tx] = in[(size_t)(k0 + ty + j) * NOUT + n0 + tx];
    __syncthreads();
#pragma unroll
    for (int j = 0; j < 32; j += 8)
        g_woutT_h[(size_t)(n0 + ty + j) * NMID + k0 + tx] = __float2half_rn(tile[tx][ty + j]);
}

__global__ void __launch_bounds__(256)
cvt_bias_kernel(const float* __restrict__ b_gen) {
    int n = blockIdx.x * 256 + threadIdx.x;
    g_biasP[permn(n)] = b_gen[n];
}

// ---------------------------------------------------------------------------
// Epilogue: deterministic split-K reduce + bias + affine LayerNorm(256)
// ---------------------------------------------------------------------------
__global__ void __launch_bounds__(256, 1)
out_ln_kernel(const float* __restrict__ b_out, const float* __restrict__ ln_w,
              const float* __restrict__ ln_b, float* __restrict__ out) {
    __shared__ float red[16];
    const int row = blockIdx.x, t = threadIdx.x;
    float v = b_out[t];
#pragma unroll
    for (int sp = 0; sp < SPLITK; ++sp)
        v += g_part[(size_t)sp * MROWS * NOUT + (size_t)row * NOUT + t];
    float s = v, ss = v * v;
    block_reduce2(s, ss, red, t);
    float mean = s * (1.f / 256.f);
    float inv  = rsqrtf(ss * (1.f / 256.f) - mean * mean + 1e-5f);
    out[(size_t)row * NOUT + t] = (v - mean) * inv * ln_w[t] + ln_b[t];
}

// ---------------------------------------------------------------------------
extern "C" void kernel_launch(void* const* d_in, const int* in_sizes, int n_in,
                              void* d_out, int out_size) {
    (void)in_sizes; (void)n_in; (void)out_size;
    const float* qf      = (const float*)d_in[0];
    const float* sampled = (const float*)d_in[1];
    const float* W_gen   = (const float*)d_in[2];
    const float* b_gen   = (const float*)d_in[3];
    const float* W_out   = (const float*)d_in[4];
    const float* b_out   = (const float*)d_in[5];
    const float* ln_w    = (const float*)d_in[6];
    const float* ln_b    = (const float*)d_in[7];

    cudaFuncSetAttribute(gemm1_h_kernel,
                         cudaFuncAttributeMaxDynamicSharedMemorySize, SMEM_BYTES);
    cudaFuncSetAttribute(gemm3_h_kernel,
                         cudaFuncAttributeMaxDynamicSharedMemorySize, SMEM_BYTES);

    cvt_qf_kernel<<<(MROWS * K1 / 4) / 256, 256>>>(qf);
    cvt_wgen_kernel<<<dim3(N1 / 32, K1 / 32), dim3(32, 8)>>>(W_gen);
    cvt_wout_kernel<<<dim3(NOUT / 32, NMID / 32), dim3(32, 8)>>>(W_out);
    cvt_bias_kernel<<<N1 / 256, 256>>>(b_gen);

    gemm1_h_kernel<<<dim3(N1 / 128, (MROWS + 127) / 128), 256, SMEM_BYTES>>>();
    mid_h_kernel<<<MROWS, 256>>>(sampled);
    gemm3_h_kernel<<<dim3(NOUT / 128, (MROWS + 127) / 128, SPLITK), 256, SMEM_BYTES>>>();
    out_ln_kernel<<<MROWS, 256>>>(b_out, ln_w, ln_b, (float*)d_out);
}